// round 7
// baseline (speedup 1.0000x reference)
#include <cuda_runtime.h>

#define BATCH 8
#define SEQ   2048
#define DIM   64
#define TQ    64      // queries per CTA
#define TK    64      // keys per tile
#define NTHR  256
#define ROWP  68      // padded row stride (floats) for Q/K/V tiles

// smem floats: sQ 64*68 + sK 64*68 + sV 64*68 + sE 64*64 = 17152 floats
// + mask 2048 bytes
#define SMEM_BYTES ((64*ROWP*3 + 64*64)*4 + SEQ)

__device__ float g_inv[BATCH*SEQ];

// packed f32x2 FMA: d = a*b + d (elementwise on packed pairs)
#define FMA2(d, a, b) asm("fma.rn.f32x2 %0, %1, %2, %0;" : "+l"(d) : "l"(a), "l"(b))
__device__ __forceinline__ unsigned long long pack2(float lo, float hi) {
    unsigned long long r;
    asm("mov.b64 %0, {%1, %2};" : "=l"(r) : "f"(lo), "f"(hi));
    return r;
}
__device__ __forceinline__ float lo32(unsigned long long u) { return __uint_as_float((unsigned)u); }
__device__ __forceinline__ float hi32(unsigned long long u) { return __uint_as_float((unsigned)(u >> 32)); }

__global__ void __launch_bounds__(NTHR, 3)
attn_main_kernel(const float* __restrict__ key,
                 const float* __restrict__ query,
                 const float* __restrict__ value,
                 const int*   __restrict__ qmask,
                 float* __restrict__ out_ctx,
                 float* __restrict__ out_attn)
{
    extern __shared__ float sm[];
    float* sQ = sm;                       // [64][68]
    float* sK = sQ + 64*ROWP;             // [64][68]
    float* sV = sK + 64*ROWP;             // [64][68]
    float* sE = sV + 64*ROWP;             // [64][64]
    unsigned char* sM = (unsigned char*)(sE + 64*64);  // [2048]

    const int b  = blockIdx.y;
    const int q0 = blockIdx.x * TQ;
    const int t  = threadIdx.x;
    const int ty = t >> 4;                // 0..15 -> q rows 4*ty..+3
    const int tx = t & 15;                // 0..15

    // ---- stage Q (scaled by 1/sqrt(64) = 0.125), mask flags ----
    {
        const float4* qg = (const float4*)(query + ((size_t)b*SEQ + q0)*DIM);
        #pragma unroll
        for (int i = t; i < TQ*DIM/4; i += NTHR) {
            int r = i >> 4, c = i & 15;
            float4 v = qg[i];
            v.x *= 0.125f; v.y *= 0.125f; v.z *= 0.125f; v.w *= 0.125f;
            *(float4*)(sQ + r*ROWP + c*4) = v;
        }
        const int* mg = qmask + (size_t)b*SEQ;
        for (int i = t; i < SEQ; i += NTHR)
            sM[i] = (unsigned char)(mg[i] != 0);
    }

    unsigned long long ctx2[4][2];
    #pragma unroll
    for (int qi = 0; qi < 4; qi++) { ctx2[qi][0] = 0ull; ctx2[qi][1] = 0ull; }
    float rowsum[4] = {0.f, 0.f, 0.f, 0.f};

    const float* kg_base = key   + (size_t)b*SEQ*DIM;
    const float* vg_base = value + (size_t)b*SEQ*DIM;
    float* attn_base = out_attn + ((size_t)b*SEQ + q0)*SEQ;

    for (int kt = 0; kt < SEQ; kt += TK) {
        __syncthreads();   // prev PV / e-write done before overwriting tiles
        // ---- stage K,V tiles [64][64] -> [64][68] ----
        {
            const float4* kg = (const float4*)(kg_base + (size_t)kt*DIM);
            const float4* vg = (const float4*)(vg_base + (size_t)kt*DIM);
            #pragma unroll
            for (int i = t; i < TK*DIM/4; i += NTHR) {
                int r = i >> 4, c = i & 15;
                *(float4*)(sK + r*ROWP + c*4) = kg[i];
                *(float4*)(sV + r*ROWP + c*4) = vg[i];
            }
        }
        __syncthreads();

        // ---- QK^T: thread tile 4q x 4k (k = tx + 16j), packed f32x2 ----
        unsigned long long acc[16];
        #pragma unroll
        for (int i = 0; i < 16; i++) acc[i] = 0ull;

        #pragma unroll 4
        for (int d4 = 0; d4 < 16; d4++) {
            ulonglong2 k2[4];
            #pragma unroll
            for (int j = 0; j < 4; j++)
                k2[j] = *(const ulonglong2*)(sK + (tx + 16*j)*ROWP + d4*4);
            #pragma unroll
            for (int qi = 0; qi < 4; qi++) {
                ulonglong2 q2 = *(const ulonglong2*)(sQ + (4*ty + qi)*ROWP + d4*4);
                #pragma unroll
                for (int j = 0; j < 4; j++) {
                    FMA2(acc[qi*4 + j], q2.x, k2[j].x);
                    FMA2(acc[qi*4 + j], q2.y, k2[j].y);
                }
            }
        }
        // ---- exp + mask, STS to sE, rowsum ----
        #pragma unroll
        for (int j = 0; j < 4; j++) {
            int kk = tx + 16*j;
            unsigned char flag = sM[kt + kk];
            #pragma unroll
            for (int qi = 0; qi < 4; qi++) {
                unsigned long long a = acc[qi*4 + j];
                float s = lo32(a) + hi32(a);
                float e = flag ? 0.0f : __expf(s);
                rowsum[qi] += e;
                sE[(4*ty + qi)*64 + kk] = e;
            }
        }
        __syncthreads();

        // ---- write unnormalized e tile to gmem (coalesced) ----
        #pragma unroll
        for (int i = t; i < TQ*TK/4; i += NTHR) {
            int r = i >> 4, c = i & 15;
            float4 e4 = *(const float4*)(sE + r*64 + c*4);
            *(float4*)(attn_base + (size_t)r*SEQ + kt + c*4) = e4;
        }

        // ---- PV: ctx[4q][d=4tx..+3] += e * V ----
        #pragma unroll 2
        for (int k = 0; k < TK; k++) {
            ulonglong2 v2 = *(const ulonglong2*)(sV + k*ROWP + tx*4);
            #pragma unroll
            for (int qi = 0; qi < 4; qi++) {
                float e = sE[(4*ty + qi)*64 + k];
                unsigned long long ee = pack2(e, e);
                FMA2(ctx2[qi][0], ee, v2.x);
                FMA2(ctx2[qi][1], ee, v2.y);
            }
        }
    }

    // ---- reduce rowsums across tx (16-lane groups), write inv, store ctx ----
    #pragma unroll
    for (int qi = 0; qi < 4; qi++) {
        float s = rowsum[qi];
        #pragma unroll
        for (int o = 8; o > 0; o >>= 1)
            s += __shfl_down_sync(0xffffffffu, s, o, 16);
        s = __shfl_sync(0xffffffffu, s, 0, 16);   // broadcast group sum
        float inv = 1.0f / s;
        if (tx == 0) g_inv[(size_t)b*SEQ + q0 + 4*ty + qi] = inv;
        float4 c;
        c.x = lo32(ctx2[qi][0]) * inv;
        c.y = hi32(ctx2[qi][0]) * inv;
        c.z = lo32(ctx2[qi][1]) * inv;
        c.w = hi32(ctx2[qi][1]) * inv;
        *(float4*)(out_ctx + ((size_t)b*SEQ + q0 + 4*ty + qi)*DIM + tx*4) = c;
    }
}

// normalize attention rows: attn[row][:] *= g_inv[row]
__global__ void __launch_bounds__(256)
attn_scale_kernel(float* __restrict__ attn)
{
    const int row = blockIdx.x;
    const float s = g_inv[row];
    float4* p = (float4*)(attn + (size_t)row*SEQ);
    #pragma unroll
    for (int i = threadIdx.x; i < SEQ/4; i += 256) {
        float4 v = p[i];
        v.x *= s; v.y *= s; v.z *= s; v.w *= s;
        p[i] = v;
    }
}

extern "C" void kernel_launch(void* const* d_in, const int* in_sizes, int n_in,
                              void* d_out, int out_size)
{
    const float* key   = (const float*)d_in[0];
    const float* query = (const float*)d_in[1];
    const float* value = (const float*)d_in[2];
    const int*   qmask = (const int*)d_in[3];

    float* out_ctx  = (float*)d_out;
    float* out_attn = (float*)d_out + (size_t)BATCH*SEQ*DIM;

    cudaFuncSetAttribute(attn_main_kernel,
                         cudaFuncAttributeMaxDynamicSharedMemorySize, SMEM_BYTES);

    dim3 grid(SEQ / TQ, BATCH);
    attn_main_kernel<<<grid, NTHR, SMEM_BYTES>>>(key, query, value, qmask,
                                                 out_ctx, out_attn);
    attn_scale_kernel<<<BATCH*SEQ, 256>>>(out_attn);
}

// round 8
// speedup vs baseline: 1.0508x; 1.0508x over previous
#include <cuda_runtime.h>

#define BATCH 8
#define SEQ   2048
#define DIM   64
#define TQ    64      // queries per CTA
#define TK    64      // keys per tile
#define NTHR  256
#define ROWP  68      // padded row stride (floats) for Q/K tiles

// smem floats: sQ 64*68 + sK 64*68 + sVt 64*64 + sE 64*64 + s_inv 64 = 16960
// + mask 2048 bytes
#define SMEM_BYTES (16960*4 + SEQ)

// packed f32x2 FMA: d = a*b + d (elementwise on packed pairs)
#define FMA2(d, a, b) asm("fma.rn.f32x2 %0, %1, %2, %0;" : "+l"(d) : "l"(a), "l"(b))
__device__ __forceinline__ float lo32(unsigned long long u) { return __uint_as_float((unsigned)u); }
__device__ __forceinline__ float hi32(unsigned long long u) { return __uint_as_float((unsigned)(u >> 32)); }

__global__ void __launch_bounds__(NTHR, 3)
attn_fused_kernel(const float* __restrict__ key,
                  const float* __restrict__ query,
                  const float* __restrict__ value,
                  const int*   __restrict__ qmask,
                  float* __restrict__ out_ctx,
                  float*              out_attn)
{
    extern __shared__ float sm[];
    float* sQ   = sm;                       // [64][68]
    float* sK   = sQ + 64*ROWP;             // [64][68]
    float* sVt  = sK + 64*ROWP;             // [64][64] transposed V, chunk-swizzled
    float* sE   = sVt + 64*64;              // [64][64]
    float* sInv = sE + 64*64;               // [64]
    unsigned char* sM = (unsigned char*)(sInv + 64);   // [2048]

    const int b  = blockIdx.y;
    const int q0 = blockIdx.x * TQ;
    const int t  = threadIdx.x;
    const int ty = t >> 4;                // 0..15 -> q rows 4*ty..+3
    const int tx = t & 15;                // 0..15

    // ---- stage Q (scaled by 1/sqrt(64) = 0.125), mask flags ----
    {
        const float4* qg = (const float4*)(query + ((size_t)b*SEQ + q0)*DIM);
        #pragma unroll
        for (int i = t; i < TQ*DIM/4; i += NTHR) {
            int r = i >> 4, c = i & 15;
            float4 v = qg[i];
            v.x *= 0.125f; v.y *= 0.125f; v.z *= 0.125f; v.w *= 0.125f;
            *(float4*)(sQ + r*ROWP + c*4) = v;
        }
        const int* mg = qmask + (size_t)b*SEQ;
        for (int i = t; i < SEQ; i += NTHR)
            sM[i] = (unsigned char)(mg[i] != 0);
    }

    float ctxf[4][4];                     // persistent context accum (folded)
    #pragma unroll
    for (int qi = 0; qi < 4; qi++)
        #pragma unroll
        for (int dd = 0; dd < 4; dd++) ctxf[qi][dd] = 0.0f;
    float rowsum[4] = {0.f, 0.f, 0.f, 0.f};

    const float* kg_base = key   + (size_t)b*SEQ*DIM;
    const float* vg_base = value + (size_t)b*SEQ*DIM;
    float* attn_base = out_attn + ((size_t)b*SEQ + q0)*SEQ;

    for (int kt = 0; kt < SEQ; kt += TK) {
        __syncthreads();   // prev tile's PV / e-write done before overwriting
        // ---- stage K [64][68]; V transposed+swizzled into sVt[d][k] ----
        {
            const float4* kg = (const float4*)(kg_base + (size_t)kt*DIM);
            const float4* vg = (const float4*)(vg_base + (size_t)kt*DIM);
            #pragma unroll
            for (int i = t; i < TK*DIM/4; i += NTHR) {
                int r = i >> 4;           // k row
                int c = i & 15;           // d4 group
                *(float4*)(sK + r*ROWP + c*4) = kg[i];
                float4 vv = vg[i];
                // sVt[d][k] at d*64 + ((k>>2)^(d>>2))*4 + (k&3); d=4c+j -> d>>2=c
                float* dst = sVt + (4*c)*64 + (((r >> 2) ^ c) << 2) + (r & 3);
                dst[0]   = vv.x;
                dst[64]  = vv.y;
                dst[128] = vv.z;
                dst[192] = vv.w;
            }
        }
        __syncthreads();

        // ---- QK^T: thread tile 4q x 4k (k = tx + 16j), packed f32x2 ----
        {
            unsigned long long acc[16];
            #pragma unroll
            for (int i = 0; i < 16; i++) acc[i] = 0ull;

            #pragma unroll 4
            for (int d4 = 0; d4 < 16; d4++) {
                ulonglong2 k2[4];
                #pragma unroll
                for (int j = 0; j < 4; j++)
                    k2[j] = *(const ulonglong2*)(sK + (tx + 16*j)*ROWP + d4*4);
                #pragma unroll
                for (int qi = 0; qi < 4; qi++) {
                    ulonglong2 q2 = *(const ulonglong2*)(sQ + (4*ty + qi)*ROWP + d4*4);
                    #pragma unroll
                    for (int j = 0; j < 4; j++) {
                        FMA2(acc[qi*4 + j], q2.x, k2[j].x);
                        FMA2(acc[qi*4 + j], q2.y, k2[j].y);
                    }
                }
            }
            // ---- exp + mask, STS to sE, rowsum ----
            #pragma unroll
            for (int j = 0; j < 4; j++) {
                int kk = tx + 16*j;
                unsigned char flag = sM[kt + kk];
                #pragma unroll
                for (int qi = 0; qi < 4; qi++) {
                    unsigned long long a = acc[qi*4 + j];
                    float s = lo32(a) + hi32(a);
                    float e = flag ? 0.0f : __expf(s);
                    rowsum[qi] += e;
                    sE[(4*ty + qi)*64 + kk] = e;
                }
            }
        }
        __syncthreads();

        // ---- write unnormalized e tile to gmem (coalesced) ----
        #pragma unroll
        for (int i = t; i < TQ*TK/4; i += NTHR) {
            int r = i >> 4, c = i & 15;
            float4 e4 = *(const float4*)(sE + r*64 + c*4);
            *(float4*)(attn_base + (size_t)r*SEQ + kt + c*4) = e4;
        }

        // ---- PV: k-pair packed. ctx[4q][4tx..+3] += e * V ----
        {
            unsigned long long acc2[4][4];   // [qi][dd], pairs over k
            #pragma unroll
            for (int qi = 0; qi < 4; qi++)
                #pragma unroll
                for (int dd = 0; dd < 4; dd++) acc2[qi][dd] = 0ull;

            #pragma unroll 4
            for (int kb = 0; kb < 16; kb++) {
                ulonglong2 vt[4];
                #pragma unroll
                for (int dd = 0; dd < 4; dd++)
                    vt[dd] = *(const ulonglong2*)(sVt + (4*tx + dd)*64 + ((kb ^ tx) << 2));
                #pragma unroll
                for (int qi = 0; qi < 4; qi++) {
                    ulonglong2 e2 = *(const ulonglong2*)(sE + (4*ty + qi)*64 + kb*4);
                    #pragma unroll
                    for (int dd = 0; dd < 4; dd++) {
                        FMA2(acc2[qi][dd], e2.x, vt[dd].x);
                        FMA2(acc2[qi][dd], e2.y, vt[dd].y);
                    }
                }
            }
            #pragma unroll
            for (int qi = 0; qi < 4; qi++)
                #pragma unroll
                for (int dd = 0; dd < 4; dd++)
                    ctxf[qi][dd] += lo32(acc2[qi][dd]) + hi32(acc2[qi][dd]);
        }
    }

    // ---- reduce rowsums across tx (16-lane groups), write inv + ctx ----
    #pragma unroll
    for (int qi = 0; qi < 4; qi++) {
        float s = rowsum[qi];
        #pragma unroll
        for (int o = 8; o > 0; o >>= 1)
            s += __shfl_down_sync(0xffffffffu, s, o, 16);
        s = __shfl_sync(0xffffffffu, s, 0, 16);   // broadcast group sum
        float inv = 1.0f / s;
        if (tx == 0) sInv[4*ty + qi] = inv;
        float4 c;
        c.x = ctxf[qi][0] * inv;
        c.y = ctxf[qi][1] * inv;
        c.z = ctxf[qi][2] * inv;
        c.w = ctxf[qi][3] * inv;
        *(float4*)(out_ctx + ((size_t)b*SEQ + q0 + 4*ty + qi)*DIM + tx*4) = c;
    }

    // ---- normalize this CTA's attn slab in place (L2-hot re-read) ----
    __syncthreads();
    #pragma unroll 4
    for (int i = t; i < TQ*SEQ/4; i += NTHR) {
        int r = i >> 9;           // / (SEQ/4)
        int c = i & 511;
        float inv = sInv[r];
        float4* p = (float4*)(attn_base + (size_t)r*SEQ) + c;
        float4 v = *p;
        v.x *= inv; v.y *= inv; v.z *= inv; v.w *= inv;
        *p = v;
    }
}

extern "C" void kernel_launch(void* const* d_in, const int* in_sizes, int n_in,
                              void* d_out, int out_size)
{
    const float* key   = (const float*)d_in[0];
    const float* query = (const float*)d_in[1];
    const float* value = (const float*)d_in[2];
    const int*   qmask = (const int*)d_in[3];

    float* out_ctx  = (float*)d_out;
    float* out_attn = (float*)d_out + (size_t)BATCH*SEQ*DIM;

    cudaFuncSetAttribute(attn_fused_kernel,
                         cudaFuncAttributeMaxDynamicSharedMemorySize, SMEM_BYTES);

    dim3 grid(SEQ / TQ, BATCH);
    attn_fused_kernel<<<grid, NTHR, SMEM_BYTES>>>(key, query, value, qmask,
                                                  out_ctx, out_attn);
}

// round 10
// speedup vs baseline: 1.3604x; 1.2946x over previous
#include <cuda_runtime.h>
#include <cstdint>

#define BATCH 8
#define SEQ   2048
#define DIM   64
#define TM    128
#define TN    64
#define NTILES 32
#define NTHR  256

// ---- smem layout (float offsets) ----
#define KST  68
#define VST  72
#define EST  68
#define KBUF (64*KST)          // 4352
#define VBUF (64*VST)          // 4608
#define F_KHI 0
#define F_KLO (F_KHI + 2*KBUF) // 8704
#define F_VHI (F_KLO + 2*KBUF) // 17408
#define F_VLO (F_VHI + 2*VBUF) // 26624
#define F_SE  (F_VLO + 2*VBUF) // 35840
#define F_MSK (F_SE + TM*EST)  // 44544
#define F_INV (F_MSK + SEQ)    // 46592
#define SMEM_FLOATS (F_INV + TM) // 46720
#define SMEM_BYTES (SMEM_FLOATS*4)

__device__ __forceinline__ uint32_t tf32u(float x) {
    uint32_t u; asm("cvt.rna.tf32.f32 %0, %1;" : "=r"(u) : "f"(x)); return u;
}
__device__ __forceinline__ float uf(uint32_t u) { return __uint_as_float(u); }
__device__ __forceinline__ uint32_t fu(float f) { return __float_as_uint(f); }

// D += A(16x8 tf32) * B(8x8 tf32), fp32 accumulate
__device__ __forceinline__ void mma8(float* c, const uint32_t* a, uint32_t b0, uint32_t b1) {
    asm volatile("mma.sync.aligned.m16n8k8.row.col.f32.tf32.tf32.f32 "
        "{%0,%1,%2,%3},{%4,%5,%6,%7},{%8,%9},{%0,%1,%2,%3};"
        : "+f"(c[0]), "+f"(c[1]), "+f"(c[2]), "+f"(c[3])
        : "r"(a[0]), "r"(a[1]), "r"(a[2]), "r"(a[3]), "r"(b0), "r"(b1));
}

__device__ __forceinline__ void storeK(float* sm, int buf, int idx, float4 v) {
    int row = idx >> 4, c = (idx & 15) * 4;
    float4 h, l;
    h.x = uf(tf32u(v.x)); l.x = v.x - h.x;
    h.y = uf(tf32u(v.y)); l.y = v.y - h.y;
    h.z = uf(tf32u(v.z)); l.z = v.z - h.z;
    h.w = uf(tf32u(v.w)); l.w = v.w - h.w;
    *(float4*)(sm + F_KHI + buf*KBUF + row*KST + c) = h;
    *(float4*)(sm + F_KLO + buf*KBUF + row*KST + c) = l;
}
__device__ __forceinline__ void storeV(float* sm, int buf, int idx, float4 v) {
    int row = idx >> 4, c = (idx & 15) * 4;
    float4 h, l;
    h.x = uf(tf32u(v.x)); l.x = v.x - h.x;
    h.y = uf(tf32u(v.y)); l.y = v.y - h.y;
    h.z = uf(tf32u(v.z)); l.z = v.z - h.z;
    h.w = uf(tf32u(v.w)); l.w = v.w - h.w;
    *(float4*)(sm + F_VHI + buf*VBUF + row*VST + c) = h;
    *(float4*)(sm + F_VLO + buf*VBUF + row*VST + c) = l;
}

__global__ void __launch_bounds__(NTHR, 1)
attn_mma_kernel(const float* __restrict__ key,
                const float* __restrict__ query,
                const float* __restrict__ value,
                const int*   __restrict__ qmask,
                float* __restrict__ out_ctx,
                float*              out_attn)
{
    extern __shared__ float sm[];
    const int b  = blockIdx.y;
    const int q0 = blockIdx.x * TM;
    const int t  = threadIdx.x;
    const int wq = t >> 5;          // warp 0..7 -> q rows 16*wq..+15
    const int lane = t & 31;
    const int r4 = lane >> 2;       // 0..7
    const int c4 = lane & 3;        // 0..3

    const float* kg_base = key   + (size_t)b * SEQ * DIM;
    const float* vg_base = value + (size_t)b * SEQ * DIM;
    float* attn_base = out_attn + ((size_t)b * SEQ + q0) * SEQ;

    // ---- stage tile 0, mask ----
    {
        const float4* kg = (const float4*)kg_base;
        const float4* vg = (const float4*)vg_base;
        #pragma unroll
        for (int it = 0; it < 4; it++) {
            int idx = t + 256 * it;
            storeK(sm, 0, idx, kg[idx]);
            storeV(sm, 0, idx, vg[idx]);
        }
        const int* mg = qmask + (size_t)b * SEQ;
        float* msk = sm + F_MSK;
        for (int i = t; i < SEQ; i += NTHR)
            msk[i] = mg[i] ? -1e30f : 0.0f;
    }

    // ---- persistent Q frags (hi/lo), scaled by 0.125 ----
    uint32_t qh[8][4], ql[8][4];
    {
        const float* qr = query + ((size_t)b * SEQ + q0 + 16 * wq) * DIM;
        #pragma unroll
        for (int ks = 0; ks < 8; ks++) {
            float x0 = qr[(size_t)r4 * DIM + ks * 8 + c4] * 0.125f;
            float x1 = qr[(size_t)(r4 + 8) * DIM + ks * 8 + c4] * 0.125f;
            float x2 = qr[(size_t)r4 * DIM + ks * 8 + c4 + 4] * 0.125f;
            float x3 = qr[(size_t)(r4 + 8) * DIM + ks * 8 + c4 + 4] * 0.125f;
            qh[ks][0] = tf32u(x0); ql[ks][0] = fu(x0 - uf(qh[ks][0]));
            qh[ks][1] = tf32u(x1); ql[ks][1] = fu(x1 - uf(qh[ks][1]));
            qh[ks][2] = tf32u(x2); ql[ks][2] = fu(x2 - uf(qh[ks][2]));
            qh[ks][3] = tf32u(x3); ql[ks][3] = fu(x3 - uf(qh[ks][3]));
        }
    }
    __syncthreads();

    float cacc[4][2][4];            // ctx^T frags [mt][nq][4]
    #pragma unroll
    for (int mt = 0; mt < 4; mt++)
        #pragma unroll
        for (int nq = 0; nq < 2; nq++)
            #pragma unroll
            for (int i = 0; i < 4; i++) cacc[mt][nq][i] = 0.0f;
    float rs0 = 0.0f, rs8 = 0.0f;   // rowsums for q rows 16wq+r4, +8

    float* sE = sm + F_SE;
    const float* msk = sm + F_MSK;

    for (int kt = 0; kt < NTILES; kt++) {
        const int buf = kt & 1;
        // ---- prefetch next tile into regs ----
        float4 pk[4], pv[4];
        if (kt + 1 < NTILES) {
            const float4* kg = (const float4*)kg_base + (size_t)(kt + 1) * TN * DIM / 4;
            const float4* vg = (const float4*)vg_base + (size_t)(kt + 1) * TN * DIM / 4;
            #pragma unroll
            for (int it = 0; it < 4; it++) {
                pk[it] = kg[t + 256 * it];
                pv[it] = vg[t + 256 * it];
            }
        }

        // ---- QK^T: S[16q x 64key], 3xTF32 ----
        float sacc[8][4];
        #pragma unroll
        for (int nt = 0; nt < 8; nt++)
            #pragma unroll
            for (int i = 0; i < 4; i++) sacc[nt][i] = 0.0f;

        const float* kh_b = sm + F_KHI + buf * KBUF + r4 * KST + c4;
        const float* kl_b = sm + F_KLO + buf * KBUF + r4 * KST + c4;
        #pragma unroll
        for (int ks = 0; ks < 8; ks++) {
            #pragma unroll
            for (int nt = 0; nt < 8; nt++) {
                const float* ph = kh_b + nt * 8 * KST + ks * 8;
                const float* pl = kl_b + nt * 8 * KST + ks * 8;
                uint32_t b0h = fu(ph[0]), b1h = fu(ph[4]);
                uint32_t b0l = fu(pl[0]), b1l = fu(pl[4]);
                mma8(sacc[nt], qh[ks], b0h, b1h);
                mma8(sacc[nt], qh[ks], b0l, b1l);
                mma8(sacc[nt], ql[ks], b0h, b1h);
            }
        }

        // ---- epilogue: exp+mask, e -> gmem (float2) + sE, rowsum ----
        {
            float* ar0 = attn_base + (size_t)(16 * wq + r4) * SEQ + kt * 64;
            float* ar8 = ar0 + (size_t)8 * SEQ;
            float* se0 = sE + (16 * wq + r4) * EST;
            float* se8 = se0 + 8 * EST;
            #pragma unroll
            for (int nt = 0; nt < 8; nt++) {
                int kloc = nt * 8 + 2 * c4;
                float m0 = msk[kt * 64 + kloc];
                float m1 = msk[kt * 64 + kloc + 1];
                float e0 = __expf(sacc[nt][0] + m0);
                float e1 = __expf(sacc[nt][1] + m1);
                float e2 = __expf(sacc[nt][2] + m0);
                float e3 = __expf(sacc[nt][3] + m1);
                rs0 += e0 + e1; rs8 += e2 + e3;
                *(float2*)(ar0 + kloc) = make_float2(e0, e1);
                *(float2*)(ar8 + kloc) = make_float2(e2, e3);
                *(float2*)(se0 + kloc) = make_float2(e0, e1);
                *(float2*)(se8 + kloc) = make_float2(e2, e3);
            }
        }
        __syncwarp();

        // ---- PV (transposed): ctx^T[64dim x 16q] += V^T * P^T, 3xTF32 ----
        {
            const float* vh_b = sm + F_VHI + buf * VBUF + c4 * VST + r4;
            const float* vl_b = sm + F_VLO + buf * VBUF + c4 * VST + r4;
            const float* se_b = sE + (16 * wq + r4) * EST + c4;
            #pragma unroll
            for (int ks = 0; ks < 8; ks++) {
                uint32_t bh[2][2], bl[2][2];
                #pragma unroll
                for (int nq = 0; nq < 2; nq++) {
                    float p0 = se_b[nq * 8 * EST + ks * 8];
                    float p1 = se_b[nq * 8 * EST + ks * 8 + 4];
                    bh[nq][0] = tf32u(p0); bl[nq][0] = fu(p0 - uf(bh[nq][0]));
                    bh[nq][1] = tf32u(p1); bl[nq][1] = fu(p1 - uf(bh[nq][1]));
                }
                #pragma unroll
                for (int mt = 0; mt < 4; mt++) {
                    const float* ah_p = vh_b + ks * 8 * VST + mt * 16;
                    const float* al_p = vl_b + ks * 8 * VST + mt * 16;
                    uint32_t ah[4], al[4];
                    ah[0] = fu(ah_p[0]);           al[0] = fu(al_p[0]);
                    ah[1] = fu(ah_p[8]);           al[1] = fu(al_p[8]);
                    ah[2] = fu(ah_p[4 * VST]);     al[2] = fu(al_p[4 * VST]);
                    ah[3] = fu(ah_p[4 * VST + 8]); al[3] = fu(al_p[4 * VST + 8]);
                    #pragma unroll
                    for (int nq = 0; nq < 2; nq++) {
                        mma8(cacc[mt][nq], ah, bh[nq][0], bh[nq][1]);
                        mma8(cacc[mt][nq], ah, bl[nq][0], bl[nq][1]);
                        mma8(cacc[mt][nq], al, bh[nq][0], bh[nq][1]);
                    }
                }
            }
        }

        // ---- store prefetched tile into other buffer ----
        if (kt + 1 < NTILES) {
            const int buf2 = (kt + 1) & 1;
            #pragma unroll
            for (int it = 0; it < 4; it++) {
                int idx = t + 256 * it;
                storeK(sm, buf2, idx, pk[it]);
                storeV(sm, buf2, idx, pv[it]);
            }
        }
        __syncthreads();
    }

    // ---- rowsum reduce (quad shfl), write inv ----
    rs0 += __shfl_xor_sync(0xffffffffu, rs0, 1);
    rs0 += __shfl_xor_sync(0xffffffffu, rs0, 2);
    rs8 += __shfl_xor_sync(0xffffffffu, rs8, 1);
    rs8 += __shfl_xor_sync(0xffffffffu, rs8, 2);
    if (c4 == 0) {
        sm[F_INV + 16 * wq + r4]     = 1.0f / rs0;
        sm[F_INV + 16 * wq + r4 + 8] = 1.0f / rs8;
    }
    __syncthreads();

    // ---- ctx out (normalized) ----
    {
        const float* sInv = sm + F_INV;
        #pragma unroll
        for (int nq = 0; nq < 2; nq++) {
            int qloc = 16 * wq + nq * 8 + 2 * c4;
            float i0 = sInv[qloc], i1 = sInv[qloc + 1];
            float* o0 = out_ctx + ((size_t)b * SEQ + q0 + qloc) * DIM;
            float* o1 = o0 + DIM;
            #pragma unroll
            for (int mt = 0; mt < 4; mt++) {
                int dimr = mt * 16 + r4;
                o0[dimr]     = cacc[mt][nq][0] * i0;
                o1[dimr]     = cacc[mt][nq][1] * i1;
                o0[dimr + 8] = cacc[mt][nq][2] * i0;
                o1[dimr + 8] = cacc[mt][nq][3] * i1;
            }
        }
    }

    // ---- normalize this CTA's attn slab in place (L2-hot) ----
    {
        const float* sInv = sm + F_INV;
        #pragma unroll 4
        for (int i = t; i < TM * SEQ / 4; i += NTHR) {
            int r = i >> 9;            // / (SEQ/4)
            int c = i & 511;
            float inv = sInv[r];
            float4* p = (float4*)(attn_base + (size_t)r * SEQ) + c;
            float4 v = *p;
            v.x *= inv; v.y *= inv; v.z *= inv; v.w *= inv;
            *p = v;
        }
    }
}

extern "C" void kernel_launch(void* const* d_in, const int* in_sizes, int n_in,
                              void* d_out, int out_size)
{
    const float* key   = (const float*)d_in[0];
    const float* query = (const float*)d_in[1];
    const float* value = (const float*)d_in[2];
    const int*   qmask = (const int*)d_in[3];

    float* out_ctx  = (float*)d_out;
    float* out_attn = (float*)d_out + (size_t)BATCH * SEQ * DIM;

    cudaFuncSetAttribute(attn_mma_kernel,
                         cudaFuncAttributeMaxDynamicSharedMemorySize, SMEM_BYTES);

    dim3 grid(SEQ / TM, BATCH);
    attn_mma_kernel<<<grid, NTHR, SMEM_BYTES>>>(key, query, value, qmask,
                                                out_ctx, out_attn);
}